// round 2
// baseline (speedup 1.0000x reference)
#include <cuda_runtime.h>

// Problem constants (fixed shapes for A2C_loss_64518998720812)
static constexpr int Nn = 8192;   // instances
static constexpr int Pp = 8192;   // proxies
static constexpr int Dd = 256;    // embed dim
static constexpr int Cc = 1000;   // classes

// GEMM tiling
static constexpr int BM = 128;
static constexpr int BN = 128;
static constexpr int BK = 16;
static constexpr int PITCH = 132;            // padded smem row pitch (floats)
static constexpr int SMTILE = BK * PITCH;    // one stage of a tile
static constexpr int TILES_PER_BLOCK = 8;    // column tiles per block
static constexpr int COLS_PER_BLOCK = BN * TILES_PER_BLOCK; // 1024
static constexpr int SPLITS = Pp / COLS_PER_BLOCK;          // 8
static constexpr int ROW_TILES = Nn / BM;                   // 64
static constexpr int KT_COUNT = Dd / BK;                    // 16

// Device scratch (no allocations allowed)
__device__ float g_xn[Nn * Dd];
__device__ float g_yn[Pp * Dd];
__device__ float g_ap[Nn];
__device__ float g_an[Nn];
__device__ float g_pc[Nn];
__device__ float g_hc[Nn];

// ---------------------------------------------------------------------------
// Zero the per-row accumulators
// ---------------------------------------------------------------------------
__global__ void init_kernel() {
    int i = blockIdx.x * blockDim.x + threadIdx.x;
    if (i < Nn) {
        g_ap[i] = 0.0f;
        g_an[i] = 0.0f;
        g_pc[i] = 0.0f;
        g_hc[i] = 0.0f;
    }
}

// ---------------------------------------------------------------------------
// Row-normalize inst_embed -> g_xn and inst_proxy -> g_yn
// One block per row, 64 threads, each handles one float4 (D=256).
// norm = max(||v||, 1e-8) to match torch CosineSimilarity eps semantics.
// ---------------------------------------------------------------------------
__global__ void normalize_kernel(const float* __restrict__ x,
                                 const float* __restrict__ y) {
    int row = blockIdx.x;
    const float* src;
    float* dst;
    if (row < Nn) {
        src = x + (size_t)row * Dd;
        dst = g_xn + (size_t)row * Dd;
    } else {
        int r = row - Nn;
        src = y + (size_t)r * Dd;
        dst = g_yn + (size_t)r * Dd;
    }
    int t = threadIdx.x; // 0..63
    float4 v = reinterpret_cast<const float4*>(src)[t];
    float ss = v.x * v.x + v.y * v.y + v.z * v.z + v.w * v.w;
    #pragma unroll
    for (int off = 16; off > 0; off >>= 1)
        ss += __shfl_down_sync(0xffffffffu, ss, off);
    __shared__ float s[2];
    if ((t & 31) == 0) s[t >> 5] = ss;
    __syncthreads();
    float total = s[0] + s[1];
    float inv = 1.0f / fmaxf(sqrtf(total), 1e-8f);
    v.x *= inv; v.y *= inv; v.z *= inv; v.w *= inv;
    reinterpret_cast<float4*>(dst)[t] = v;
}

// ---------------------------------------------------------------------------
// Tile load helpers: load a 128x16 slab of a row-major [*,256] matrix into
// registers (global, coalesced float4s) and store transposed into smem as
// sm[k][m] with padded pitch.
// ---------------------------------------------------------------------------
__device__ __forceinline__ void load_regs(const float* __restrict__ base, int k0,
                                          float4& v0, float4& v1) {
    int tid = threadIdx.x;
    int i0 = tid;
    int i1 = tid + 256;
    v0 = *reinterpret_cast<const float4*>(base + (i0 >> 2) * Dd + k0 + ((i0 & 3) << 2));
    v1 = *reinterpret_cast<const float4*>(base + (i1 >> 2) * Dd + k0 + ((i1 & 3) << 2));
}

__device__ __forceinline__ void store_tile(float* sm, const float4& v0, const float4& v1) {
    int tid = threadIdx.x;
    int i0 = tid;
    int i1 = tid + 256;
    int m0 = i0 >> 2, k0 = (i0 & 3) << 2;
    sm[(k0 + 0) * PITCH + m0] = v0.x;
    sm[(k0 + 1) * PITCH + m0] = v0.y;
    sm[(k0 + 2) * PITCH + m0] = v0.z;
    sm[(k0 + 3) * PITCH + m0] = v0.w;
    int m1 = i1 >> 2, k1 = (i1 & 3) << 2;
    sm[(k1 + 0) * PITCH + m1] = v1.x;
    sm[(k1 + 1) * PITCH + m1] = v1.y;
    sm[(k1 + 2) * PITCH + m1] = v1.z;
    sm[(k1 + 3) * PITCH + m1] = v1.w;
}

// ---------------------------------------------------------------------------
// Fused GEMM + masked per-row reductions.
// Grid: ROW_TILES * SPLITS blocks, 256 threads.
// Block (rt, cs): rows [rt*128, rt*128+128), cols [cs*1024, cs*1024+1024).
// Each thread: 8x8 microtile, split as rows {ty*4..+3, 64+ty*4..+3},
// cols {tx*4..+3, 64+tx*4..+3} for conflict-free float4 smem reads.
// ---------------------------------------------------------------------------
__global__ __launch_bounds__(256)
void a2c_main(const int* __restrict__ labels,
              const int* __restrict__ labelsP,
              const int* __restrict__ realList,
              const int* __restrict__ isRealPtr,
              const float* __restrict__ att) {
    __shared__ float As[2 * SMTILE];
    __shared__ float Bs[2 * SMTILE];
    __shared__ int sLp[COLS_PER_BLOCK];

    const int tid = threadIdx.x;
    const int tx = tid & 15;
    const int ty = tid >> 4;
    const int rt = blockIdx.x & (ROW_TILES - 1);
    const int cs = blockIdx.x >> 6;
    const int rb = rt * BM;
    const int cb = cs * COLS_PER_BLOCK;
    const bool useReal = (isRealPtr[0] != 0);

    // Column labels with real-mask folded in: lp = -1 => excluded entirely.
    for (int idx = tid; idx < COLS_PER_BLOCK; idx += 256) {
        int gc = cb + idx;
        int lp = labelsP[gc];
        if (useReal && realList[gc] == 0) lp = -1;
        sLp[idx] = lp;
    }

    int li[8], liOff[8];
    #pragma unroll
    for (int i = 0; i < 8; i++) {
        int r = rb + ((i < 4) ? ty * 4 + i : 64 + ty * 4 + (i - 4));
        li[i] = labels[r];
        liOff[i] = li[i] * Cc;
    }

    float rap[8], ran[8], rpc[8], rhc[8];
    #pragma unroll
    for (int i = 0; i < 8; i++) { rap[i] = 0.f; ran[i] = 0.f; rpc[i] = 0.f; rhc[i] = 0.f; }

    const float* Abase = g_xn + rb * Dd;

    for (int ct = 0; ct < TILES_PER_BLOCK; ct++) {
        const float* Bbase = g_yn + (cb + ct * BN) * Dd;

        float c[8][8];
        #pragma unroll
        for (int i = 0; i < 8; i++)
            #pragma unroll
            for (int j = 0; j < 8; j++)
                c[i][j] = 0.0f;

        float4 a0, a1, b0, b1;
        load_regs(Abase, 0, a0, a1);
        load_regs(Bbase, 0, b0, b1);
        store_tile(As, a0, a1);
        store_tile(Bs, b0, b1);
        __syncthreads();

        int st = 0;
        for (int kt = 0; kt < KT_COUNT; kt++) {
            if (kt + 1 < KT_COUNT) {
                load_regs(Abase, (kt + 1) * BK, a0, a1);
                load_regs(Bbase, (kt + 1) * BK, b0, b1);
            }
            const float* Ak = As + st * SMTILE;
            const float* Bk = Bs + st * SMTILE;
            #pragma unroll
            for (int k = 0; k < BK; k++) {
                float4 la0 = *reinterpret_cast<const float4*>(Ak + k * PITCH + ty * 4);
                float4 la1 = *reinterpret_cast<const float4*>(Ak + k * PITCH + 64 + ty * 4);
                float4 lb0 = *reinterpret_cast<const float4*>(Bk + k * PITCH + tx * 4);
                float4 lb1 = *reinterpret_cast<const float4*>(Bk + k * PITCH + 64 + tx * 4);
                float a[8] = {la0.x, la0.y, la0.z, la0.w, la1.x, la1.y, la1.z, la1.w};
                float b[8] = {lb0.x, lb0.y, lb0.z, lb0.w, lb1.x, lb1.y, lb1.z, lb1.w};
                #pragma unroll
                for (int i = 0; i < 8; i++)
                    #pragma unroll
                    for (int j = 0; j < 8; j++)
                        c[i][j] = fmaf(a[i], b[j], c[i][j]);
            }
            if (kt + 1 < KT_COUNT) {
                store_tile(As + (st ^ 1) * SMTILE, a0, a1);
                store_tile(Bs + (st ^ 1) * SMTILE, b0, b1);
                __syncthreads();
                st ^= 1;
            }
        }

        // Epilogue: fold this 128x128 tile of dist into per-row stats.
        int lbase = ct * BN;
        #pragma unroll
        for (int j = 0; j < 8; j++) {
            int jc = (j < 4) ? tx * 4 + j : 64 + tx * 4 + (j - 4);
            int lp = sLp[lbase + jc];
            if (lp >= 0) {
                #pragma unroll
                for (int i = 0; i < 8; i++) {
                    float d = 1.0f - c[i][j];
                    if (li[i] == lp) {
                        rap[i] += fmaxf(d - 0.05f, 0.0f);
                        rpc[i] += 1.0f;
                    } else {
                        float av = __ldg(att + liOff[i] + lp) * 0.5f + 0.4f;
                        if (d < av) {
                            ran[i] += av - d;
                            rhc[i] += 1.0f;
                        }
                    }
                }
            }
        }
    }

    // Reduce across the 16 threads (tx) sharing each row, then accumulate.
    #pragma unroll
    for (int i = 0; i < 8; i++) {
        float vap = rap[i], van = ran[i], vpc = rpc[i], vhc = rhc[i];
        #pragma unroll
        for (int off = 8; off > 0; off >>= 1) {
            vap += __shfl_down_sync(0xffffffffu, vap, off, 16);
            van += __shfl_down_sync(0xffffffffu, van, off, 16);
            vpc += __shfl_down_sync(0xffffffffu, vpc, off, 16);
            vhc += __shfl_down_sync(0xffffffffu, vhc, off, 16);
        }
        if (tx == 0) {
            int r = rb + ((i < 4) ? ty * 4 + i : 64 + ty * 4 + (i - 4));
            atomicAdd(&g_ap[r], vap);
            atomicAdd(&g_an[r], van);
            atomicAdd(&g_pc[r], vpc);
            atomicAdd(&g_hc[r], vhc);
        }
    }
}

// ---------------------------------------------------------------------------
// Finalize: per-row loss, mean over rows.
// ---------------------------------------------------------------------------
__global__ void finalize_kernel(float* __restrict__ out) {
    __shared__ float s[256];
    float acc = 0.0f;
    for (int r = threadIdx.x; r < Nn; r += 256) {
        float lap = g_ap[r] / (g_pc[r] + 1e-5f);
        float lan = g_an[r] / (g_hc[r] + 1e-5f);
        acc += lap + lan;
    }
    s[threadIdx.x] = acc;
    __syncthreads();
    #pragma unroll
    for (int o = 128; o > 0; o >>= 1) {
        if (threadIdx.x < o) s[threadIdx.x] += s[threadIdx.x + o];
        __syncthreads();
    }
    if (threadIdx.x == 0) out[0] = s[0] / (float)Nn;
}

// ---------------------------------------------------------------------------
// Launch
// inputs: 0 inst_embed [N*D] f32, 1 labels [N] i32, 2 inst_proxy [P*D] f32,
//         3 labels_proxy [P] i32, 4 margin (unused), 5 alpha (unused),
//         6 real_list [P] i32, 7 is_real [1] i32, 8 att_distance [C*C] f32
// ---------------------------------------------------------------------------
extern "C" void kernel_launch(void* const* d_in, const int* in_sizes, int n_in,
                              void* d_out, int out_size) {
    const float* x       = (const float*)d_in[0];
    const int*   labels  = (const int*)d_in[1];
    const float* y       = (const float*)d_in[2];
    const int*   labelsP = (const int*)d_in[3];
    const int*   realL   = (const int*)d_in[6];
    const int*   isReal  = (const int*)d_in[7];
    const float* att     = (const float*)d_in[8];
    float* out = (float*)d_out;

    init_kernel<<<(Nn + 255) / 256, 256>>>();
    normalize_kernel<<<Nn + Pp, 64>>>(x, y);
    a2c_main<<<ROW_TILES * SPLITS, 256>>>(labels, labelsP, realL, isReal, att);
    finalize_kernel<<<1, 256>>>(out);
}

// round 4
// speedup vs baseline: 2.3535x; 2.3535x over previous
#include <cuda_runtime.h>
#include <cuda_bf16.h>
#include <cstdint>

// ---------------------------------------------------------------------------
// Problem constants
// ---------------------------------------------------------------------------
static constexpr int Nn = 8192;
static constexpr int Pp = 8192;
static constexpr int Dd = 256;   // K
static constexpr int Cc = 1000;

// Tiling
static constexpr int TM = 128;               // CTA tile M
static constexpr int TN = 128;               // CTA tile N
static constexpr int COL_SPLITS = 2;
static constexpr int COLS_PER_CTA = Pp / COL_SPLITS;       // 4096
static constexpr int NT = COLS_PER_CTA / TN;               // 32 tiles per CTA
static constexpr int ROW_TILES = Nn / TM;                  // 64
static constexpr int NUM_K_STEPS = Dd / 16;                // 16

// SMEM: A tile / B tiles are 128 rows x 512B, stored as 4 blocks of
// [128 rows x 128B], SW128-swizzled within each block.
static constexpr int TILE_BYTES  = TM * Dd * 2;            // 65536
static constexpr int BLOCK_BYTES = 16384;
static constexpr int SMEM_A  = 0;
static constexpr int SMEM_B0 = SMEM_A + TILE_BYTES;
static constexpr int SMEM_B1 = SMEM_B0 + TILE_BYTES;
static constexpr int SMEM_LP = SMEM_B1 + TILE_BYTES;       // 2 x 128 ints
static constexpr int SMEM_TOTAL = SMEM_LP + 2 * TN * 4;    // 197632

// ---------------------------------------------------------------------------
// Device scratch
// ---------------------------------------------------------------------------
__device__ __nv_bfloat16 g_xn[Nn * Dd];
__device__ __nv_bfloat16 g_yn[Pp * Dd];
__device__ float g_ap[Nn];
__device__ float g_an[Nn];
__device__ float g_pc[Nn];
__device__ float g_hc[Nn];

// ---------------------------------------------------------------------------
// PTX helpers (compute_100-safe: cp.async, ldmatrix, mma.sync only)
// ---------------------------------------------------------------------------
__device__ __forceinline__ uint32_t smem_u32(const void* p) {
    uint32_t a;
    asm("{ .reg .u64 t; cvta.to.shared.u64 t, %1; cvt.u32.u64 %0, t; }" : "=r"(a) : "l"(p));
    return a;
}
__device__ __forceinline__ uint32_t swz128(uint32_t off) {
    return off ^ ((off >> 3) & 0x70);
}
__device__ __forceinline__ void cp_async16(uint32_t dst, const void* src) {
    asm volatile("cp.async.cg.shared.global [%0], [%1], 16;" :: "r"(dst), "l"(src));
}
#define CP_COMMIT()  asm volatile("cp.async.commit_group;" ::: "memory")
#define CP_WAIT(n)   asm volatile("cp.async.wait_group %0;" :: "n"(n) : "memory")

__device__ __forceinline__ void ldsm_x4(uint32_t* r, uint32_t addr) {
    asm volatile("ldmatrix.sync.aligned.m8n8.x4.shared.b16 {%0,%1,%2,%3}, [%4];"
                 : "=r"(r[0]), "=r"(r[1]), "=r"(r[2]), "=r"(r[3]) : "r"(addr));
}
__device__ __forceinline__ void mma_bf16(float* d, const uint32_t* a,
                                         uint32_t b0, uint32_t b1) {
    asm volatile(
        "mma.sync.aligned.m16n8k16.row.col.f32.bf16.bf16.f32 "
        "{%0,%1,%2,%3}, {%4,%5,%6,%7}, {%8,%9}, {%0,%1,%2,%3};"
        : "+f"(d[0]), "+f"(d[1]), "+f"(d[2]), "+f"(d[3])
        : "r"(a[0]), "r"(a[1]), "r"(a[2]), "r"(a[3]), "r"(b0), "r"(b1));
}

// smem tile element address: (row, kbyte) with kbyte in [0,512)
__device__ __forceinline__ uint32_t tile_addr(uint32_t base, int row, int kbyte) {
    return base + (kbyte >> 7) * BLOCK_BYTES + swz128(row * 128 + (kbyte & 127));
}

// ---------------------------------------------------------------------------
// init: zero accumulators
// ---------------------------------------------------------------------------
__global__ void init_kernel() {
    int i = blockIdx.x * blockDim.x + threadIdx.x;
    if (i < Nn) { g_ap[i] = 0.f; g_an[i] = 0.f; g_pc[i] = 0.f; g_hc[i] = 0.f; }
}

// ---------------------------------------------------------------------------
// normalize rows of x (Nn) and y (Pp) -> bf16 scratch
// ---------------------------------------------------------------------------
__global__ void normalize_kernel(const float* __restrict__ x,
                                 const float* __restrict__ y) {
    int row = blockIdx.x;
    const float* src;
    __nv_bfloat16* dst;
    if (row < Nn) { src = x + (size_t)row * Dd; dst = g_xn + (size_t)row * Dd; }
    else { int r = row - Nn; src = y + (size_t)r * Dd; dst = g_yn + (size_t)r * Dd; }
    int t = threadIdx.x; // 0..63
    float4 v = reinterpret_cast<const float4*>(src)[t];
    float ss = v.x * v.x + v.y * v.y + v.z * v.z + v.w * v.w;
    #pragma unroll
    for (int off = 16; off > 0; off >>= 1)
        ss += __shfl_down_sync(0xffffffffu, ss, off);
    __shared__ float s[2];
    if ((t & 31) == 0) s[t >> 5] = ss;
    __syncthreads();
    float inv = 1.0f / fmaxf(sqrtf(s[0] + s[1]), 1e-8f);
    __nv_bfloat162 lo = __floats2bfloat162_rn(v.x * inv, v.y * inv);
    __nv_bfloat162 hi = __floats2bfloat162_rn(v.z * inv, v.w * inv);
    uint2 pk;
    pk.x = *reinterpret_cast<uint32_t*>(&lo);
    pk.y = *reinterpret_cast<uint32_t*>(&hi);
    reinterpret_cast<uint2*>(dst)[t] = pk;
}

// ---------------------------------------------------------------------------
// Async tile loader: 128 rows x 256 bf16 into 4 SW128 blocks. 256 thr x 16.
// ---------------------------------------------------------------------------
__device__ __forceinline__ void load_tile(const __nv_bfloat16* gbase, uint32_t sbase) {
    int tid = threadIdx.x;
    #pragma unroll
    for (int it = 0; it < 16; it++) {
        int idx = tid + it * 256;
        int r = idx >> 5;        // row
        int w = idx & 31;        // 16B granule within row (32 per row)
        int c = w >> 3;          // 128B block
        int g = w & 7;           // granule within block row
        const char* src = reinterpret_cast<const char*>(gbase + (size_t)r * Dd) + w * 16;
        uint32_t dst = sbase + c * BLOCK_BYTES + swz128(r * 128 + g * 16);
        cp_async16(dst, src);
    }
}

// ---------------------------------------------------------------------------
// Main fused kernel: mma.sync bf16 GEMM + masked per-row reduction epilogue.
// Grid = ROW_TILES*COL_SPLITS = 128 CTAs, 256 threads (8 warps, 4M x 2N).
// Warp tile 32x64. Thread owns 4 rows x 16 cols of the 128x128 tile.
// ---------------------------------------------------------------------------
__global__ __launch_bounds__(256)
void a2c_main(const int* __restrict__ labels,
              const int* __restrict__ labelsP,
              const int* __restrict__ realList,
              const int* __restrict__ isRealPtr,
              const float* __restrict__ att) {
    extern __shared__ __align__(1024) unsigned char smem[];
    const uint32_t sb = smem_u32(smem);
    const int tid = threadIdx.x;
    const int wid = tid >> 5;
    const int lane = tid & 31;
    const int warpM = wid & 3;        // 0..3 -> rows warpM*32..+31
    const int warpN = wid >> 2;       // 0..1 -> cols warpN*64..+63
    const int g   = lane >> 2;        // group id 0..7
    const int tig = lane & 3;         // thread-in-group

    const int rt = blockIdx.x >> 1;
    const int cspl = blockIdx.x & 1;
    const int rb = rt * TM;
    const int cb = cspl * COLS_PER_CTA;
    const bool useReal = (isRealPtr[0] != 0);

    int* sLp = reinterpret_cast<int*>(smem + SMEM_LP);

    // Prologue: A tile + B tile 0 async, labels tile 0
    load_tile(g_xn + (size_t)rb * Dd, sb + SMEM_A);
    load_tile(g_yn + (size_t)cb * Dd, sb + SMEM_B0);
    CP_COMMIT();
    if (tid < TN) {
        int gc = cb + tid;
        int lp = labelsP[gc];
        if (useReal && realList[gc] == 0) lp = -1;
        sLp[tid] = lp;
    }

    // This thread's 4 row-slots: rs = mt*2+h -> row warpM*32 + mt*16 + h*8 + g
    int liOff4[4];
    int li4[4];
    #pragma unroll
    for (int rs = 0; rs < 4; rs++) {
        int rloc = warpM * 32 + (rs >> 1) * 16 + (rs & 1) * 8 + g;
        li4[rs] = labels[rb + rloc];
        liOff4[rs] = li4[rs] * Cc;
    }
    float rap[4] = {0.f, 0.f, 0.f, 0.f};
    float ran[4] = {0.f, 0.f, 0.f, 0.f};
    float rpc[4] = {0.f, 0.f, 0.f, 0.f};
    float rhc[4] = {0.f, 0.f, 0.f, 0.f};

    // ldmatrix lane addressing (constant parts)
    const int aRow = warpM * 32 + (lane & 15);        // + mt*16
    const int bNrow = warpN * 64 + (lane & 7) + ((lane >> 3) & 1) * 8;  // + pair*16
    const int kHalf = (lane >> 4) * 16;               // +16B for k8-15 lanes

    for (int t = 0; t < NT; t++) {
        const int buf = t & 1;
        const uint32_t bsm = sb + (buf ? SMEM_B1 : SMEM_B0);

        // prefetch t+1
        if (t + 1 < NT) {
            const uint32_t nb = sb + ((t + 1) & 1 ? SMEM_B1 : SMEM_B0);
            load_tile(g_yn + (size_t)(cb + (t + 1) * TN) * Dd, nb);
            CP_COMMIT();
            if (tid < TN) {
                int gc = cb + (t + 1) * TN + tid;
                int lp = labelsP[gc];
                if (useReal && realList[gc] == 0) lp = -1;
                sLp[((t + 1) & 1) * TN + tid] = lp;
            }
            CP_WAIT(1);
        } else {
            CP_WAIT(0);
        }
        __syncthreads();

        // ---- compute 128x128 tile: c[mt][nt][4] ----
        float c[2][8][4];
        #pragma unroll
        for (int mt = 0; mt < 2; mt++)
            #pragma unroll
            for (int nt = 0; nt < 8; nt++)
                #pragma unroll
                for (int e = 0; e < 4; e++)
                    c[mt][nt][e] = 0.f;

        #pragma unroll 4
        for (int ks = 0; ks < NUM_K_STEPS; ks++) {
            const int kb = ks * 32 + kHalf;
            uint32_t a[2][4];
            ldsm_x4(a[0], tile_addr(sb + SMEM_A, aRow, kb));
            ldsm_x4(a[1], tile_addr(sb + SMEM_A, aRow + 16, kb));
            uint32_t b[4][4];
            #pragma unroll
            for (int p = 0; p < 4; p++)
                ldsm_x4(b[p], tile_addr(bsm, bNrow + p * 16, kb));
            #pragma unroll
            for (int mt = 0; mt < 2; mt++)
                #pragma unroll
                for (int p = 0; p < 4; p++) {
                    mma_bf16(c[mt][2 * p],     a[mt], b[p][0], b[p][2]);
                    mma_bf16(c[mt][2 * p + 1], a[mt], b[p][1], b[p][3]);
                }
        }

        // ---- epilogue: fold into per-row stats ----
        const int lpb = buf * TN;
        #pragma unroll
        for (int nt = 0; nt < 8; nt++) {
            const int col0 = warpN * 64 + nt * 8 + 2 * tig;
            const int lp0 = sLp[lpb + col0];
            const int lp1 = sLp[lpb + col0 + 1];
            #pragma unroll
            for (int mt = 0; mt < 2; mt++) {
                #pragma unroll
                for (int h = 0; h < 2; h++) {
                    const int rs = mt * 2 + h;
                    #pragma unroll
                    for (int e = 0; e < 2; e++) {
                        const int lp = e ? lp1 : lp0;
                        if (lp >= 0) {
                            float d = 1.0f - c[mt][nt][h * 2 + e];
                            if (lp == li4[rs]) {
                                rap[rs] += fmaxf(d - 0.05f, 0.0f);
                                rpc[rs] += 1.0f;
                            } else {
                                float av = __ldg(att + liOff4[rs] + lp) * 0.5f + 0.4f;
                                if (d < av) { ran[rs] += av - d; rhc[rs] += 1.0f; }
                            }
                        }
                    }
                }
            }
        }
        __syncthreads();   // all reads of buf + sLp[buf] done before overwrite
    }

    // reduce over the 4 lanes sharing each row, then atomics (x2 warpN, x2 CTA)
    #pragma unroll
    for (int rs = 0; rs < 4; rs++) {
        float vap = rap[rs], van = ran[rs], vpc = rpc[rs], vhc = rhc[rs];
        #pragma unroll
        for (int off = 2; off > 0; off >>= 1) {
            vap += __shfl_down_sync(0xffffffffu, vap, off, 4);
            van += __shfl_down_sync(0xffffffffu, van, off, 4);
            vpc += __shfl_down_sync(0xffffffffu, vpc, off, 4);
            vhc += __shfl_down_sync(0xffffffffu, vhc, off, 4);
        }
        if (tig == 0) {
            int rglob = rb + warpM * 32 + (rs >> 1) * 16 + (rs & 1) * 8 + g;
            atomicAdd(&g_ap[rglob], vap);
            atomicAdd(&g_an[rglob], van);
            atomicAdd(&g_pc[rglob], vpc);
            atomicAdd(&g_hc[rglob], vhc);
        }
    }
}

// ---------------------------------------------------------------------------
// finalize: per-row loss, mean over rows
// ---------------------------------------------------------------------------
__global__ void finalize_kernel(float* __restrict__ out) {
    __shared__ float s[1024];
    float acc = 0.0f;
    for (int r = threadIdx.x; r < Nn; r += 1024) {
        float lap = g_ap[r] / (g_pc[r] + 1e-5f);
        float lan = g_an[r] / (g_hc[r] + 1e-5f);
        acc += lap + lan;
    }
    s[threadIdx.x] = acc;
    __syncthreads();
    #pragma unroll
    for (int o = 512; o > 0; o >>= 1) {
        if (threadIdx.x < o) s[threadIdx.x] += s[threadIdx.x + o];
        __syncthreads();
    }
    if (threadIdx.x == 0) out[0] = s[0] / (float)Nn;
}

// ---------------------------------------------------------------------------
// launch
// ---------------------------------------------------------------------------
extern "C" void kernel_launch(void* const* d_in, const int* in_sizes, int n_in,
                              void* d_out, int out_size) {
    const float* x       = (const float*)d_in[0];
    const int*   labels  = (const int*)d_in[1];
    const float* y       = (const float*)d_in[2];
    const int*   labelsP = (const int*)d_in[3];
    const int*   realL   = (const int*)d_in[6];
    const int*   isReal  = (const int*)d_in[7];
    const float* att     = (const float*)d_in[8];
    float* out = (float*)d_out;

    static bool attr_set = false;
    if (!attr_set) {
        cudaFuncSetAttribute(a2c_main, cudaFuncAttributeMaxDynamicSharedMemorySize,
                             SMEM_TOTAL);
        attr_set = true;
    }

    init_kernel<<<(Nn + 255) / 256, 256>>>();
    normalize_kernel<<<Nn + Pp, 64>>>(x, y);
    a2c_main<<<ROW_TILES * COL_SPLITS, 256, SMEM_TOTAL>>>(labels, labelsP, realL,
                                                          isReal, att);
    finalize_kernel<<<1, 1024>>>(out);
}

// round 5
// speedup vs baseline: 4.8786x; 2.0730x over previous
#include <cuda_runtime.h>
#include <cuda_bf16.h>
#include <cstdint>

// ---------------------------------------------------------------------------
// Problem constants
// ---------------------------------------------------------------------------
static constexpr int Nn = 8192;
static constexpr int Pp = 8192;
static constexpr int Dd = 256;   // K
static constexpr int Cc = 1000;

// Tiling
static constexpr int TM = 128;               // CTA tile M
static constexpr int TN = 128;               // CTA tile N
static constexpr int COL_SPLITS = 2;
static constexpr int COLS_PER_CTA = Pp / COL_SPLITS;       // 4096
static constexpr int NT = COLS_PER_CTA / TN;               // 32 tiles per CTA
static constexpr int ROW_TILES = Nn / TM;                  // 64
static constexpr int NUM_K_STEPS = Dd / 16;                // 16

// SMEM: A tile / B tiles are 128 rows x 512B, stored as 4 blocks of
// [128 rows x 128B], SW128-swizzled within each block.
static constexpr int TILE_BYTES  = TM * Dd * 2;            // 65536
static constexpr int BLOCK_BYTES = 16384;
static constexpr int SMEM_A  = 0;
static constexpr int SMEM_B0 = SMEM_A + TILE_BYTES;
static constexpr int SMEM_B1 = SMEM_B0 + TILE_BYTES;
static constexpr int SMEM_LP = SMEM_B1 + TILE_BYTES;       // 2 x 128 ints
static constexpr int SMEM_TOTAL = SMEM_LP + 2 * TN * 4;    // 197632

// ---------------------------------------------------------------------------
// Device scratch
// ---------------------------------------------------------------------------
__device__ __nv_bfloat16 g_xn[Nn * Dd];
__device__ __nv_bfloat16 g_yn[Pp * Dd];
__device__ float g_ap[Nn];
__device__ float g_an[Nn];
__device__ float g_pc[Nn];
__device__ float g_hc[Nn];

// ---------------------------------------------------------------------------
// PTX helpers (compute_100-safe: cp.async, ldmatrix, mma.sync only)
// ---------------------------------------------------------------------------
__device__ __forceinline__ uint32_t smem_u32(const void* p) {
    uint32_t a;
    asm("{ .reg .u64 t; cvta.to.shared.u64 t, %1; cvt.u32.u64 %0, t; }" : "=r"(a) : "l"(p));
    return a;
}
__device__ __forceinline__ uint32_t swz128(uint32_t off) {
    return off ^ ((off >> 3) & 0x70);
}
__device__ __forceinline__ void cp_async16(uint32_t dst, const void* src) {
    asm volatile("cp.async.cg.shared.global [%0], [%1], 16;" :: "r"(dst), "l"(src));
}
#define CP_COMMIT()  asm volatile("cp.async.commit_group;" ::: "memory")
#define CP_WAIT(n)   asm volatile("cp.async.wait_group %0;" :: "n"(n) : "memory")

__device__ __forceinline__ void ldsm_x4(uint32_t* r, uint32_t addr) {
    asm volatile("ldmatrix.sync.aligned.m8n8.x4.shared.b16 {%0,%1,%2,%3}, [%4];"
                 : "=r"(r[0]), "=r"(r[1]), "=r"(r[2]), "=r"(r[3]) : "r"(addr));
}
__device__ __forceinline__ void mma_bf16(float* d, const uint32_t* a,
                                         uint32_t b0, uint32_t b1) {
    asm volatile(
        "mma.sync.aligned.m16n8k16.row.col.f32.bf16.bf16.f32 "
        "{%0,%1,%2,%3}, {%4,%5,%6,%7}, {%8,%9}, {%0,%1,%2,%3};"
        : "+f"(d[0]), "+f"(d[1]), "+f"(d[2]), "+f"(d[3])
        : "r"(a[0]), "r"(a[1]), "r"(a[2]), "r"(a[3]), "r"(b0), "r"(b1));
}

// smem tile element address: (row, kbyte) with kbyte in [0,512)
__device__ __forceinline__ uint32_t tile_addr(uint32_t base, int row, int kbyte) {
    return base + (kbyte >> 7) * BLOCK_BYTES + swz128(row * 128 + (kbyte & 127));
}

// ---------------------------------------------------------------------------
// init: zero accumulators + output
// ---------------------------------------------------------------------------
__global__ void init_kernel(float* __restrict__ out) {
    int i = blockIdx.x * blockDim.x + threadIdx.x;
    if (i < Nn) { g_ap[i] = 0.f; g_an[i] = 0.f; g_pc[i] = 0.f; g_hc[i] = 0.f; }
    if (i == 0) out[0] = 0.f;
}

// ---------------------------------------------------------------------------
// normalize rows of x (Nn) and y (Pp) -> bf16 scratch
// ---------------------------------------------------------------------------
__global__ void normalize_kernel(const float* __restrict__ x,
                                 const float* __restrict__ y) {
    int row = blockIdx.x;
    const float* src;
    __nv_bfloat16* dst;
    if (row < Nn) { src = x + (size_t)row * Dd; dst = g_xn + (size_t)row * Dd; }
    else { int r = row - Nn; src = y + (size_t)r * Dd; dst = g_yn + (size_t)r * Dd; }
    int t = threadIdx.x; // 0..63
    float4 v = reinterpret_cast<const float4*>(src)[t];
    float ss = v.x * v.x + v.y * v.y + v.z * v.z + v.w * v.w;
    #pragma unroll
    for (int off = 16; off > 0; off >>= 1)
        ss += __shfl_down_sync(0xffffffffu, ss, off);
    __shared__ float s[2];
    if ((t & 31) == 0) s[t >> 5] = ss;
    __syncthreads();
    float inv = 1.0f / fmaxf(sqrtf(s[0] + s[1]), 1e-8f);
    __nv_bfloat162 lo = __floats2bfloat162_rn(v.x * inv, v.y * inv);
    __nv_bfloat162 hi = __floats2bfloat162_rn(v.z * inv, v.w * inv);
    uint2 pk;
    pk.x = *reinterpret_cast<uint32_t*>(&lo);
    pk.y = *reinterpret_cast<uint32_t*>(&hi);
    reinterpret_cast<uint2*>(dst)[t] = pk;
}

// ---------------------------------------------------------------------------
// Async tile loader: 128 rows x 256 bf16 into 4 SW128 blocks. 256 thr x 16.
// ---------------------------------------------------------------------------
__device__ __forceinline__ void load_tile(const __nv_bfloat16* gbase, uint32_t sbase) {
    int tid = threadIdx.x;
    #pragma unroll
    for (int it = 0; it < 16; it++) {
        int idx = tid + it * 256;
        int r = idx >> 5;        // row
        int w = idx & 31;        // 16B granule within row (32 per row)
        int c = w >> 3;          // 128B block
        int g = w & 7;           // granule within block row
        const char* src = reinterpret_cast<const char*>(gbase + (size_t)r * Dd) + w * 16;
        uint32_t dst = sbase + c * BLOCK_BYTES + swz128(r * 128 + g * 16);
        cp_async16(dst, src);
    }
}

// ---------------------------------------------------------------------------
// Main fused kernel: mma.sync bf16 GEMM + branchless masked epilogue.
// Grid = ROW_TILES*COL_SPLITS = 128 CTAs, 256 threads (8 warps, 4M x 2N).
// Warp tile 32x64. Thread owns 4 rows x 16 cols of the 128x128 tile.
// ---------------------------------------------------------------------------
__global__ __launch_bounds__(256)
void a2c_main(const int* __restrict__ labels,
              const int* __restrict__ labelsP,
              const int* __restrict__ realList,
              const int* __restrict__ isRealPtr,
              const float* __restrict__ att) {
    extern __shared__ __align__(1024) unsigned char smem[];
    const uint32_t sb = smem_u32(smem);
    const int tid = threadIdx.x;
    const int wid = tid >> 5;
    const int lane = tid & 31;
    const int warpM = wid & 3;        // 0..3 -> rows warpM*32..+31
    const int warpN = wid >> 2;       // 0..1 -> cols warpN*64..+63
    const int g   = lane >> 2;        // group id 0..7
    const int tig = lane & 3;         // thread-in-group

    const int rt = blockIdx.x >> 1;
    const int cspl = blockIdx.x & 1;
    const int rb = rt * TM;
    const int cb = cspl * COLS_PER_CTA;
    const bool useReal = (isRealPtr[0] != 0);

    int* sLp = reinterpret_cast<int*>(smem + SMEM_LP);

    // Prologue: A tile + B tile 0 async (one group), labels tile 0
    load_tile(g_xn + (size_t)rb * Dd, sb + SMEM_A);
    load_tile(g_yn + (size_t)cb * Dd, sb + SMEM_B0);
    CP_COMMIT();
    if (tid < TN) {
        int gc = cb + tid;
        int lp = labelsP[gc];
        if (useReal && realList[gc] == 0) lp = -1;
        sLp[tid] = lp;
    }

    // This thread's 4 row-slots: rs = mt*2+h -> row warpM*32 + mt*16 + h*8 + g
    int liOff4[4];
    int li4[4];
    #pragma unroll
    for (int rs = 0; rs < 4; rs++) {
        int rloc = warpM * 32 + (rs >> 1) * 16 + (rs & 1) * 8 + g;
        li4[rs] = labels[rb + rloc];
        liOff4[rs] = li4[rs] * Cc;
    }
    float rap[4] = {0.f, 0.f, 0.f, 0.f};
    float ran[4] = {0.f, 0.f, 0.f, 0.f};
    float rpc[4] = {0.f, 0.f, 0.f, 0.f};
    float rhc[4] = {0.f, 0.f, 0.f, 0.f};

    // ldmatrix lane addressing (constant parts)
    const int aRow = warpM * 32 + (lane & 15);        // + mt*16
    const int bNrow = warpN * 64 + (lane & 7) + ((lane >> 3) & 1) * 8;  // + pair*16
    const int kHalf = (lane >> 4) * 16;               // +16B for k8-15 lanes

    for (int t = 0; t < NT; t++) {
        const int buf = t & 1;
        const uint32_t bsm = sb + (buf ? SMEM_B1 : SMEM_B0);

        // tile t's cp.async group is the only outstanding one
        CP_WAIT(0);
        __syncthreads();   // single barrier per tile: data ready + prev epilogue done

        // prefetch t+1 into the other buffer (overlaps compute below)
        if (t + 1 < NT) {
            const uint32_t nb = sb + ((t + 1) & 1 ? SMEM_B1 : SMEM_B0);
            load_tile(g_yn + (size_t)(cb + (t + 1) * TN) * Dd, nb);
            CP_COMMIT();
            if (tid < TN) {
                int gc = cb + (t + 1) * TN + tid;
                int lp = labelsP[gc];
                if (useReal && realList[gc] == 0) lp = -1;
                sLp[((t + 1) & 1) * TN + tid] = lp;
            }
        }

        // ---- compute 128x128 tile: c[mt][nt][4] ----
        float c[2][8][4];
        #pragma unroll
        for (int mt = 0; mt < 2; mt++)
            #pragma unroll
            for (int nt = 0; nt < 8; nt++)
                #pragma unroll
                for (int e = 0; e < 4; e++)
                    c[mt][nt][e] = 0.f;

        #pragma unroll 4
        for (int ks = 0; ks < NUM_K_STEPS; ks++) {
            const int kb = ks * 32 + kHalf;
            uint32_t a[2][4];
            ldsm_x4(a[0], tile_addr(sb + SMEM_A, aRow, kb));
            ldsm_x4(a[1], tile_addr(sb + SMEM_A, aRow + 16, kb));
            uint32_t b[4][4];
            #pragma unroll
            for (int p = 0; p < 4; p++)
                ldsm_x4(b[p], tile_addr(bsm, bNrow + p * 16, kb));
            #pragma unroll
            for (int mt = 0; mt < 2; mt++)
                #pragma unroll
                for (int p = 0; p < 4; p++) {
                    mma_bf16(c[mt][2 * p],     a[mt], b[p][0], b[p][2]);
                    mma_bf16(c[mt][2 * p + 1], a[mt], b[p][1], b[p][3]);
                }
        }

        // ---- branchless epilogue: 8 batched att gathers per nt ----
        const int lpb = buf * TN;
        #pragma unroll
        for (int nt = 0; nt < 8; nt++) {
            const int col0 = warpN * 64 + nt * 8 + 2 * tig;
            const int lp0 = sLp[lpb + col0];
            const int lp1 = sLp[lpb + col0 + 1];
            const int clp0 = lp0 < 0 ? 0 : lp0;
            const int clp1 = lp1 < 0 ? 0 : lp1;
            // batch 8 independent gathers (MLP=8)
            float av[2][4];
            #pragma unroll
            for (int rs = 0; rs < 4; rs++) {
                av[0][rs] = __ldg(att + liOff4[rs] + clp0);
                av[1][rs] = __ldg(att + liOff4[rs] + clp1);
            }
            #pragma unroll
            for (int e = 0; e < 2; e++) {
                const int lp = e ? lp1 : lp0;
                const bool valid = (lp >= 0);
                #pragma unroll
                for (int mt = 0; mt < 2; mt++)
                    #pragma unroll
                    for (int h = 0; h < 2; h++) {
                        const int rs = mt * 2 + h;
                        const float d = 1.0f - c[mt][nt][h * 2 + e];
                        const float a = av[e][rs] * 0.5f + 0.4f;
                        const bool isPos = valid && (lp == li4[rs]);
                        const bool isHin = valid && (lp != li4[rs]) && (d < a);
                        rap[rs] += isPos ? fmaxf(d - 0.05f, 0.0f) : 0.0f;
                        rpc[rs] += isPos ? 1.0f : 0.0f;
                        ran[rs] += isHin ? (a - d) : 0.0f;
                        rhc[rs] += isHin ? 1.0f : 0.0f;
                    }
            }
        }
        // no trailing barrier: next iteration's prefetch targets the other
        // buffer/label half; the leading barrier orders buffer reuse at t+2.
    }

    // reduce over the 4 lanes sharing each row, then atomics (x2 warpN, x2 CTA)
    #pragma unroll
    for (int rs = 0; rs < 4; rs++) {
        float vap = rap[rs], van = ran[rs], vpc = rpc[rs], vhc = rhc[rs];
        #pragma unroll
        for (int off = 2; off > 0; off >>= 1) {
            vap += __shfl_down_sync(0xffffffffu, vap, off, 4);
            van += __shfl_down_sync(0xffffffffu, van, off, 4);
            vpc += __shfl_down_sync(0xffffffffu, vpc, off, 4);
            vhc += __shfl_down_sync(0xffffffffu, vhc, off, 4);
        }
        if (tig == 0) {
            int rglob = rb + warpM * 32 + (rs >> 1) * 16 + (rs & 1) * 8 + g;
            atomicAdd(&g_ap[rglob], vap);
            atomicAdd(&g_an[rglob], van);
            atomicAdd(&g_pc[rglob], vpc);
            atomicAdd(&g_hc[rglob], vhc);
        }
    }
}

// ---------------------------------------------------------------------------
// finalize: per-row loss, mean over rows. 32 blocks, atomicAdd into out
// (out zeroed by init_kernel).
// ---------------------------------------------------------------------------
__global__ void finalize_kernel(float* __restrict__ out) {
    __shared__ float s[8];
    const int rows_per_block = Nn / 32;                    // 256
    int r = blockIdx.x * rows_per_block + threadIdx.x;     // 256 threads
    float lap = g_ap[r] / (g_pc[r] + 1e-5f);
    float lan = g_an[r] / (g_hc[r] + 1e-5f);
    float acc = lap + lan;
    #pragma unroll
    for (int off = 16; off > 0; off >>= 1)
        acc += __shfl_down_sync(0xffffffffu, acc, off);
    if ((threadIdx.x & 31) == 0) s[threadIdx.x >> 5] = acc;
    __syncthreads();
    if (threadIdx.x == 0) {
        float b = 0.f;
        #pragma unroll
        for (int i = 0; i < 8; i++) b += s[i];
        atomicAdd(out, b * (1.0f / (float)Nn));
    }
}

// ---------------------------------------------------------------------------
// launch
// ---------------------------------------------------------------------------
extern "C" void kernel_launch(void* const* d_in, const int* in_sizes, int n_in,
                              void* d_out, int out_size) {
    const float* x       = (const float*)d_in[0];
    const int*   labels  = (const int*)d_in[1];
    const float* y       = (const float*)d_in[2];
    const int*   labelsP = (const int*)d_in[3];
    const int*   realL   = (const int*)d_in[6];
    const int*   isReal  = (const int*)d_in[7];
    const float* att     = (const float*)d_in[8];
    float* out = (float*)d_out;

    static bool attr_set = false;
    if (!attr_set) {
        cudaFuncSetAttribute(a2c_main, cudaFuncAttributeMaxDynamicSharedMemorySize,
                             SMEM_TOTAL);
        attr_set = true;
    }

    init_kernel<<<(Nn + 255) / 256, 256>>>(out);
    normalize_kernel<<<Nn + Pp, 64>>>(x, y);
    a2c_main<<<ROW_TILES * COL_SPLITS, 256, SMEM_TOTAL>>>(labels, labelsP, realL,
                                                          isReal, att);
    finalize_kernel<<<32, 256>>>(out);
}